// round 16
// baseline (speedup 1.0000x reference)
#include <cuda_runtime.h>
#include <cuda_fp16.h>
#include <cstdint>

// ============================================================================
// Problem constants
// ============================================================================
#define TOK   16384      // 4 * 4096 tokens
#define F     2048       // in/out features

// ============================================================================
// Device scratch (static globals — allocation-free per harness rules)
// ============================================================================
__device__ __half    g_W[F * F];       // W_eff fp16 (8.4 MB)
__device__ __half    g_X[TOK * F];     // x fp16 (67 MB)
__device__ unsigned  g_cnt[TOK / 128]; // per-token-panel conversion counters (128)
__device__ unsigned  g_fcnt[32];       // per-ot fold counters (32, target 32)

// ============================================================================
// Helpers
// ============================================================================
__device__ __forceinline__ uint32_t smem_to_u32(const void* p) {
    uint32_t a;
    asm("{ .reg .u64 t; cvta.to.shared.u64 t, %1; cvt.u32.u64 %0, t; }"
        : "=r"(a) : "l"(p));
    return a;
}

__device__ __forceinline__ unsigned ld_acquire_gpu(const unsigned* p) {
    unsigned v;
    asm volatile("ld.acquire.gpu.global.b32 %0, [%1];" : "=r"(v) : "l"(p));
    return v;
}

// ============================================================================
// Init kernel: zero rendezvous counters (fresh each graph replay).
// ============================================================================
__global__ void init_kernel() {
    int t = threadIdx.x;
    if (t < 32) g_fcnt[t] = 0;
    if (t < TOK / 128) g_cnt[t] = 0;
}

// ============================================================================
// Fused kernel, 1D grid of 3072 blocks:
//   bid <  1024 : FOLD block (ot = bid>>5, g = bid&31) — tensor-core fold,
//                 W block (ot,g) via 2 HMMA 64x64x64 GEMMs; signal g_fcnt[ot].
//   bid >= 1024 : GEMM block u = bid-1024, bx = u&15, by = u>>4.
//                 Convert 8 rows of x panel by, rendezvous on g_cnt[by] and
//                 g_fcnt[2bx] / g_fcnt[2bx+1], then R11 mainloop (128x128).
// Fold blocks all have lower bids than GEMM blocks -> scheduled first; no
// circular waits (fold has no dependencies, GEMM only consumes).
// ============================================================================
#define FS 72   // fold fp16 smem row stride (halves)

static constexpr int BM = 128, BN = 128, BK = 64, STAGES = 3;
static constexpr int A_STAGE_BYTES = BM * BK * 2;               // 16384
static constexpr int STAGE_BYTES   = (BM + BN) * BK * 2;        // 32768
static constexpr int SMEM_BYTES    = STAGES * STAGE_BYTES;      // 98304

__global__ __launch_bounds__(256, 2)
void fused_kernel(const float* __restrict__ x,
                  const float* __restrict__ stage1,
                  const float* __restrict__ stage2,
                  const float* __restrict__ mix_w,
                  float* __restrict__ out) {
    extern __shared__ char smem[];
    const int bid = blockIdx.x;
    const int tid = threadIdx.x;
    const int lane = tid & 31;

    // ======================= FOLD blocks =======================
    if (bid < 1024) {
        const int ot = bid >> 5, g = bid & 31;
        const int w = tid >> 5;
        __half* s2T = (__half*)smem;           // [oo][c]   A of GEMM1
        __half* mxT = s2T + 64 * FS;           // [dd][c]   B of GEMM1
        __half* s1s = mxT + 64 * FS;           // [c2][dd]  B of GEMM2
        __half* mTs = s1s + 64 * FS;           // [oo][dd]  M

        // loads (fp32 -> fp16, transposed where needed)
        for (int i = tid; i < 4096; i += 256) {
            int c = i >> 6, oo = i & 63;
            s2T[oo * FS + c] = __float2half_rn(stage2[(ot * 64 + c) * 64 + oo]);
        }
#pragma unroll
        for (int it = 0; it < 8; it++) {
            int i = tid + it * 256;            // (c, k) pair-gather
            int c = i >> 5, k = i & 31;
            float2 v = *(const float2*)(mix_w +
                         (size_t)(ot * 64 + c) * F + 64 * k + 2 * g);
            mxT[k * FS + c]        = __float2half_rn(v.x);
            mxT[(k + 32) * FS + c] = __float2half_rn(v.y);
        }
        for (int i = tid; i < 4096; i += 256) {
            int c2 = i >> 6, dd = i & 63;
            s1s[c2 * FS + dd] = __float2half_rn(stage1[(g * 64 + c2) * 64 + dd]);
        }
        __syncthreads();

        const int mrow = (w >> 1) * 16;
        const int ncol = (w & 1) * 32;
        const uint32_t uS2 = smem_to_u32(s2T);
        const uint32_t uMx = smem_to_u32(mxT);
        const uint32_t uS1 = smem_to_u32(s1s);
        const uint32_t uMT = smem_to_u32(mTs);

        const int aRow = mrow + (lane & 15);
        const int aChk = (lane >> 4);
        const int bOff = (lane & 7) | ((lane & 16) >> 1);
        const int bChk = (lane >> 3) & 1;

        auto gemm64 = [&](uint32_t uA, uint32_t uB, float acc[4][4]) {
#pragma unroll
            for (int fn = 0; fn < 4; fn++)
#pragma unroll
                for (int k = 0; k < 4; k++) acc[fn][k] = 0.0f;
#pragma unroll
            for (int ks = 0; ks < 4; ks++) {
                uint32_t a[4], bb[8];
                uint32_t aAddr = uA + (uint32_t)((aRow * FS + ks * 16 + aChk * 8) * 2);
                asm volatile(
                    "ldmatrix.sync.aligned.m8n8.x4.shared.b16 {%0,%1,%2,%3}, [%4];"
                    : "=r"(a[0]), "=r"(a[1]), "=r"(a[2]), "=r"(a[3]) : "r"(aAddr));
#pragma unroll
                for (int p = 0; p < 2; p++) {
                    uint32_t bAddr = uB + (uint32_t)(((ncol + p * 16 + bOff) * FS
                                        + ks * 16 + bChk * 8) * 2);
                    asm volatile(
                        "ldmatrix.sync.aligned.m8n8.x4.shared.b16 {%0,%1,%2,%3}, [%4];"
                        : "=r"(bb[p*4+0]), "=r"(bb[p*4+1]),
                          "=r"(bb[p*4+2]), "=r"(bb[p*4+3]) : "r"(bAddr));
                }
#pragma unroll
                for (int fn = 0; fn < 4; fn++) {
                    uint32_t b0 = bb[(fn >> 1) * 4 + (fn & 1) * 2];
                    uint32_t b1 = bb[(fn >> 1) * 4 + (fn & 1) * 2 + 1];
                    asm volatile(
                        "mma.sync.aligned.m16n8k16.row.col.f32.f16.f16.f32 "
                        "{%0,%1,%2,%3}, {%4,%5,%6,%7}, {%8,%9}, {%0,%1,%2,%3};"
                        : "+f"(acc[fn][0]), "+f"(acc[fn][1]),
                          "+f"(acc[fn][2]), "+f"(acc[fn][3])
                        : "r"(a[0]), "r"(a[1]), "r"(a[2]), "r"(a[3]),
                          "r"(b0), "r"(b1));
                }
            }
        };

        float acc1[4][4];
        gemm64(uS2, uMx, acc1);             // M = stage2^T x mixP
        {
            const int rr = mrow + (lane >> 2);
#pragma unroll
            for (int fn = 0; fn < 4; fn++) {
                const int cc = ncol + fn * 8 + (lane & 3) * 2;
                __half2 lo = __floats2half2_rn(acc1[fn][0], acc1[fn][1]);
                __half2 hi = __floats2half2_rn(acc1[fn][2], acc1[fn][3]);
                *(__half2*)(mTs + rr * FS + cc)       = lo;
                *(__half2*)(mTs + (rr + 8) * FS + cc) = hi;
            }
        }
        __syncthreads();

        float acc2[4][4];
        gemm64(uMT, uS1, acc2);             // W = M x stage1^T
        {
            const int rr = ot * 64 + mrow + (lane >> 2);
#pragma unroll
            for (int fn = 0; fn < 4; fn++) {
                const int cc = g * 64 + ncol + fn * 8 + (lane & 3) * 2;
                __half2 lo = __floats2half2_rn(acc2[fn][0], acc2[fn][1]);
                __half2 hi = __floats2half2_rn(acc2[fn][2], acc2[fn][3]);
                *(__half2*)(g_W + (size_t)rr * F + cc)       = lo;
                *(__half2*)(g_W + (size_t)(rr + 8) * F + cc) = hi;
            }
        }
        __threadfence();
        __syncthreads();
        if (tid == 0) atomicAdd(&g_fcnt[ot], 1u);
        return;
    }

    // ======================= GEMM blocks =======================
    const uint32_t sbase = smem_to_u32(smem);
    const int u  = bid - 1024;
    const int bx = u & 15, by = u >> 4;
    const int wid = tid >> 5;
    const int m0 = by * BM;
    const int n0 = bx * BN;
    const int wm = (wid >> 2) * 64;
    const int wn = (wid & 3) * 32;

    // ---- distributed conversion: bx owns 8 rows of panel by ----
    {
        const size_t base = ((size_t)m0 + (size_t)bx * 8) * F;
#pragma unroll 8
        for (int it = 0; it < 16; it++) {
            size_t off = base + (size_t)it * 1024 + (size_t)tid * 4;
            float4 v = *(const float4*)(x + off);
            __half2 h0 = __floats2half2_rn(v.x, v.y);
            __half2 h1 = __floats2half2_rn(v.z, v.w);
            uint2 w;
            w.x = *(uint32_t*)&h0; w.y = *(uint32_t*)&h1;
            *(uint2*)(g_X + off) = w;
        }
        __threadfence();
        __syncthreads();
        if (tid == 0) {
            atomicAdd(&g_cnt[by], 1u);
            while (ld_acquire_gpu(&g_cnt[by]) < 16u) { }
            while (ld_acquire_gpu(&g_fcnt[2 * bx]) < 32u) { }
            while (ld_acquire_gpu(&g_fcnt[2 * bx + 1]) < 32u) { }
        }
        __syncthreads();
    }

    // ---- cp.async geometry: 4 x 16B per thread per operand per stage ----
    uint32_t dst_off[4];
    size_t   srcA[4], srcB[4];
#pragma unroll
    for (int i = 0; i < 4; i++) {
        int uu = tid + 256 * i;               // 0..1023
        int row = uu >> 3, seg = uu & 7;      // 128 rows x 8 segs of 16B
        dst_off[i] = (uint32_t)(row * 128 + ((seg ^ (row & 7)) * 16));
        srcA[i] = (size_t)(m0 + row) * F + seg * 8;
        srcB[i] = (size_t)(n0 + row) * F + seg * 8;
    }
    const __half* gA = g_X;
    const __half* gB = g_W;

    auto issue_stage = [&](int kc, int st) {
        uint32_t sA = sbase + st * STAGE_BYTES;
        uint32_t sB = sA + A_STAGE_BYTES;
        const __half* pa = gA + (size_t)kc * BK;
        const __half* pb = gB + (size_t)kc * BK;
#pragma unroll
        for (int i = 0; i < 4; i++) {
            asm volatile("cp.async.cg.shared.global [%0], [%1], 16;"
                         :: "r"(sA + dst_off[i]), "l"(pa + srcA[i]) : "memory");
            asm volatile("cp.async.cg.shared.global [%0], [%1], 16;"
                         :: "r"(sB + dst_off[i]), "l"(pb + srcB[i]) : "memory");
        }
    };

    // ---- ldmatrix per-lane addressing ----
    const uint32_t aRow = (uint32_t)(wm + (lane & 15));
    const uint32_t bRow = (uint32_t)(wn + ((lane & 7) | ((lane & 16) >> 1)));
    uint32_t xsA[4], xsB[4];
#pragma unroll
    for (int ks = 0; ks < 4; ks++) {
        xsA[ks] = (uint32_t)(((ks * 2 + (lane >> 4)) ^ (lane & 7)) * 16);
        xsB[ks] = (uint32_t)(((ks * 2 + ((lane >> 3) & 1)) ^ (lane & 7)) * 16);
    }
    const uint32_t aBase = aRow * 128u;
    const uint32_t bBase = bRow * 128u;

    float acc[4][4][4];
#pragma unroll
    for (int fm = 0; fm < 4; fm++)
#pragma unroll
        for (int fn = 0; fn < 4; fn++)
#pragma unroll
            for (int k = 0; k < 4; k++) acc[fm][fn][k] = 0.0f;

    auto compute_stage = [&](int st) {
        uint32_t sA = sbase + st * STAGE_BYTES + aBase;
        uint32_t sB = sbase + st * STAGE_BYTES + A_STAGE_BYTES + bBase;
#pragma unroll
        for (int ks = 0; ks < 4; ks++) {
            uint32_t a[4][4], b[8];
#pragma unroll
            for (int fm = 0; fm < 4; fm++) {
                uint32_t addr = sA + (uint32_t)(fm * 2048) + xsA[ks];
                asm volatile(
                    "ldmatrix.sync.aligned.m8n8.x4.shared.b16 {%0,%1,%2,%3}, [%4];"
                    : "=r"(a[fm][0]), "=r"(a[fm][1]), "=r"(a[fm][2]), "=r"(a[fm][3])
                    : "r"(addr));
            }
#pragma unroll
            for (int p = 0; p < 2; p++) {
                uint32_t addr = sB + (uint32_t)(p * 2048) + xsB[ks];
                asm volatile(
                    "ldmatrix.sync.aligned.m8n8.x4.shared.b16 {%0,%1,%2,%3}, [%4];"
                    : "=r"(b[p*4+0]), "=r"(b[p*4+1]), "=r"(b[p*4+2]), "=r"(b[p*4+3])
                    : "r"(addr));
            }
#pragma unroll
            for (int fm = 0; fm < 4; fm++) {
#pragma unroll
                for (int fn = 0; fn < 4; fn++) {
                    uint32_t b0 = b[(fn >> 1) * 4 + (fn & 1) * 2];
                    uint32_t b1 = b[(fn >> 1) * 4 + (fn & 1) * 2 + 1];
                    asm volatile(
                        "mma.sync.aligned.m16n8k16.row.col.f32.f16.f16.f32 "
                        "{%0,%1,%2,%3}, {%4,%5,%6,%7}, {%8,%9}, {%0,%1,%2,%3};"
                        : "+f"(acc[fm][fn][0]), "+f"(acc[fm][fn][1]),
                          "+f"(acc[fm][fn][2]), "+f"(acc[fm][fn][3])
                        : "r"(a[fm][0]), "r"(a[fm][1]), "r"(a[fm][2]), "r"(a[fm][3]),
                          "r"(b0), "r"(b1));
                }
            }
        }
    };

    // ---- pipeline ----
    issue_stage(0, 0);
    asm volatile("cp.async.commit_group;" ::: "memory");
    issue_stage(1, 1);
    asm volatile("cp.async.commit_group;" ::: "memory");

    const int NCHUNK = F / BK;   // 32
    for (int kc = 0; kc < NCHUNK; kc++) {
        asm volatile("cp.async.wait_group 1;" ::: "memory");
        __syncthreads();
        if (kc + 2 < NCHUNK) {
            int nxt = kc + 2;
            issue_stage(nxt, nxt % STAGES);
        }
        asm volatile("cp.async.commit_group;" ::: "memory");
        compute_stage(kc % STAGES);
    }

    // ---- epilogue: direct fp32 stores ----
#pragma unroll
    for (int fm = 0; fm < 4; fm++) {
#pragma unroll
        for (int fn = 0; fn < 4; fn++) {
            int r = m0 + wm + fm * 16 + (lane >> 2);
            int c = n0 + wn + fn * 8 + (lane & 3) * 2;
            float2 v0 = make_float2(acc[fm][fn][0], acc[fm][fn][1]);
            float2 v1 = make_float2(acc[fm][fn][2], acc[fm][fn][3]);
            *(float2*)(out + (size_t)r * F + c)       = v0;
            *(float2*)(out + (size_t)(r + 8) * F + c) = v1;
        }
    }
}

// ============================================================================
// Launch
// ============================================================================
extern "C" void kernel_launch(void* const* d_in, const int* in_sizes, int n_in,
                              void* d_out, int out_size) {
    const float* x      = (const float*)d_in[0];
    const float* stage1 = (const float*)d_in[1];
    const float* stage2 = (const float*)d_in[2];
    const float* mix_w  = (const float*)d_in[3];
    float* out = (float*)d_out;

    cudaFuncSetAttribute(fused_kernel,
                         cudaFuncAttributeMaxDynamicSharedMemorySize, SMEM_BYTES);

    init_kernel<<<1, 256>>>();
    fused_kernel<<<1024 + (F / BN) * (TOK / BM), 256, SMEM_BYTES>>>(
        x, stage1, stage2, mix_w, out);
}